// round 5
// baseline (speedup 1.0000x reference)
#include <cuda_runtime.h>
#include <math.h>

#define N_NODES 100000
#define N_EDGES 1000000
#define C 64
#define N_PAD 100032            // 1563 * 64
#define SCAN_BLOCKS 98          // 98*1024 >= N_NODES
#define FLAGBIT (1 << 30)

typedef unsigned long long ull;

// ---------------- scratch (device globals; no allocation allowed) -----------
__device__ __align__(16) float g_mean[(size_t)N_PAD * C];
__device__ __align__(16) float g_h1  [(size_t)N_PAD * C];
__device__ int g_deg[N_NODES];
__device__ int g_rowptr[N_NODES + 1];
__device__ int g_cursor[N_NODES];
__device__ int g_col[N_EDGES];
__device__ int g_look[SCAN_BLOCKS];     // decoupled-lookback slots (value | FLAGBIT)

// ---------------- f32x2 packed FMA helpers ----------------------------------
__device__ __forceinline__ ull pk2(float lo, float hi) {
    ull r;
    asm("mov.b64 %0, {%1, %2};" : "=l"(r) : "f"(lo), "f"(hi));
    return r;
}
__device__ __forceinline__ ull fma2(ull a, ull b, ull c) {
    ull d;
    asm("fma.rn.f32x2 %0, %1, %2, %3;" : "=l"(d) : "l"(a), "l"(b), "l"(c));
    return d;
}
__device__ __forceinline__ void unpk2(ull v, float& lo, float& hi) {
    asm("mov.b64 {%0, %1}, %2;" : "=f"(lo), "=f"(hi) : "l"(v));
}

// ========================= CSR build =========================================
__global__ void zero_kernel() {
    int i = blockIdx.x * 1024 + threadIdx.x;
    if (i < N_NODES) g_deg[i] = 0;
    if (i < SCAN_BLOCKS) g_look[i] = 0;
}

// 4 edges per thread, vectorized index load
__global__ void deg_kernel(const int* __restrict__ dst) {
    int e4 = blockIdx.x * blockDim.x + threadIdx.x;
    if (e4 * 4 + 3 < N_EDGES) {
        int4 d = ((const int4*)dst)[e4];
        atomicAdd(&g_deg[d.x], 1);
        atomicAdd(&g_deg[d.y], 1);
        atomicAdd(&g_deg[d.z], 1);
        atomicAdd(&g_deg[d.w], 1);
    } else {
        for (int e = e4 * 4; e < N_EDGES; ++e) atomicAdd(&g_deg[dst[e]], 1);
    }
}

// single-pass scan: local warp-shuffle scan + decoupled lookback over block
// aggregates. All SCAN_BLOCKS blocks fit in one wave (98 <= 148 SMs), so
// spinning on predecessors is deadlock-free.
__global__ void __launch_bounds__(1024) scan_kernel() {
    __shared__ int swarp[32];
    __shared__ int sprefix;
    int t = threadIdx.x;
    int b = blockIdx.x;
    int i = b * 1024 + t;
    int lane = t & 31;
    int wid = t >> 5;

    int deg = (i < N_NODES) ? g_deg[i] : 0;

    // warp inclusive scan
    int v = deg;
    #pragma unroll
    for (int off = 1; off < 32; off <<= 1) {
        int u = __shfl_up_sync(0xffffffffu, v, off);
        if (lane >= off) v += u;
    }
    if (lane == 31) swarp[wid] = v;
    __syncthreads();
    if (wid == 0) {
        int w = swarp[lane];
        #pragma unroll
        for (int off = 1; off < 32; off <<= 1) {
            int u = __shfl_up_sync(0xffffffffu, w, off);
            if (lane >= off) w += u;
        }
        swarp[lane] = w;
    }
    __syncthreads();
    int incl = v + (wid > 0 ? swarp[wid - 1] : 0);   // block-local inclusive
    int total = swarp[31];

    // publish aggregate, then look back over predecessors' aggregates
    if (t == 0) atomicExch(&g_look[b], total | FLAGBIT);
    if (wid == 0) {
        int run = 0;
        for (int base = 0; base < b; base += 32) {
            int idx = base + lane;
            int a = 0;
            if (idx < b) {
                do { a = atomicAdd(&g_look[idx], 0); } while (!(a & FLAGBIT));
                a &= ~FLAGBIT;
            }
            #pragma unroll
            for (int off = 16; off > 0; off >>= 1)
                a += __shfl_xor_sync(0xffffffffu, a, off);
            run += a;
        }
        if (lane == 0) sprefix = run;
    }
    __syncthreads();

    if (i < N_NODES) {
        int gincl = sprefix + incl;
        g_rowptr[i + 1] = gincl;
        g_cursor[i] = gincl - deg;
        if (i == 0) g_rowptr[0] = 0;
    }
}

__global__ void fill_kernel(const int* __restrict__ src, const int* __restrict__ dst) {
    int e = blockIdx.x * blockDim.x + threadIdx.x;
    if (e < N_EDGES) {
        int pos = atomicAdd(&g_cursor[dst[e]], 1);
        g_col[pos] = src[e];
    }
}

// ========================= mean aggregation ==================================
// 16 threads per node (one float4 chunk each); unroll-4 with dual accumulators
// for memory-level parallelism. LAYER selects feature source device-side.
template <int LAYER>
__global__ void __launch_bounds__(256) agg_mean_kernel(const float* __restrict__ x_ext) {
    int idx = blockIdx.x * 256 + threadIdx.x;
    int n = idx >> 4;
    int c = idx & 15;
    if (n >= N_NODES) {
        ((float4*)g_mean)[(size_t)n * 16 + c] = make_float4(0.f, 0.f, 0.f, 0.f);
        return;
    }
    const float4* f4 = (LAYER == 1) ? (const float4*)x_ext : (const float4*)g_h1;
    int beg = g_rowptr[n];
    int end = g_rowptr[n + 1];
    float4 a0 = make_float4(0.f, 0.f, 0.f, 0.f);
    float4 a1 = make_float4(0.f, 0.f, 0.f, 0.f);
    int j = beg;
    for (; j + 3 < end; j += 4) {
        int s0 = g_col[j], s1 = g_col[j + 1], s2 = g_col[j + 2], s3 = g_col[j + 3];
        float4 p = f4[(size_t)s0 * 16 + c];
        float4 q = f4[(size_t)s1 * 16 + c];
        float4 r = f4[(size_t)s2 * 16 + c];
        float4 s = f4[(size_t)s3 * 16 + c];
        a0.x += p.x + q.x; a0.y += p.y + q.y; a0.z += p.z + q.z; a0.w += p.w + q.w;
        a1.x += r.x + s.x; a1.y += r.y + s.y; a1.z += r.z + s.z; a1.w += r.w + s.w;
    }
    for (; j < end; ++j) {
        int s0 = g_col[j];
        float4 p = f4[(size_t)s0 * 16 + c];
        a0.x += p.x; a0.y += p.y; a0.z += p.z; a0.w += p.w;
    }
    float inv = 1.0f / fmaxf((float)(end - beg), 1.0f);
    float4 acc;
    acc.x = (a0.x + a1.x) * inv;
    acc.y = (a0.y + a1.y) * inv;
    acc.z = (a0.z + a1.z) * inv;
    acc.w = (a0.w + a1.w) * inv;
    ((float4*)g_mean)[(size_t)n * 16 + c] = acc;
}

// ========================= node GEMM =========================================
// 256 threads/block, 64 nodes/block. Thread t: og = t&15 (outputs 4og..4og+3),
// ng = t>>4 (nodes 4ng..4ng+3). Mean/self staged as duplicated (v,v) u64 pairs;
// weights transposed so LDS.128 yields output pairs. k unrolled by 2 so node
// values load as ulonglong2 (one LDS.128 covers 2 k). smem ~100KB -> 2 blocks
// (512 threads, 16 warps) per SM.
#define SW_STRIDE 68            // floats per weight row
#define SM_STRIDE 66            // u64 per node row (even -> 16B-aligned ull2)
#define SMEM_BYTES (2*64*SW_STRIDE*4 + 2*64*SM_STRIDE*8)   // 34816+67584=102400

template <int LAYER>
__global__ void __launch_bounds__(256, 2) node_kernel(
        const float* __restrict__ x_ext,
        const float* __restrict__ Wl,
        const float* __restrict__ bias,
        const float* __restrict__ Wr,
        const float* __restrict__ w_out,
        const float* __restrict__ b_out,
        float* __restrict__ out) {
    extern __shared__ char smraw[];
    float* sWl = (float*)smraw;                       // [64][SW_STRIDE]
    float* sWr = sWl + 64 * SW_STRIDE;
    ull* sMd = (ull*)(sWr + 64 * SW_STRIDE);          // [64][SM_STRIDE]
    ull* sSd = sMd + 64 * SM_STRIDE;

    const float* selfF = (LAYER == 1) ? x_ext : (const float*)g_h1;

    int t = threadIdx.x;
    int og = t & 15;
    int ng = t >> 4;
    int base = blockIdx.x * 64;

    // stage weights transposed: sW[k*STRIDE + o] = W[o*64 + k]
    #pragma unroll
    for (int i = t; i < 64 * 64; i += 256) {
        int o = i >> 6, k = i & 63;
        sWl[k * SW_STRIDE + o] = Wl[i];
        sWr[k * SW_STRIDE + o] = Wr[i];
    }

    // stage mean/self duplicated: sMd[n*STRIDE + k] = (v, v)
    #pragma unroll
    for (int it = 0; it < 4; ++it) {
        int item = it * 256 + t;
        int n = item & 63;
        int c = item >> 6;                           // float4 chunk 0..15
        int gn = base + n;
        int cn = (LAYER == 1) ? min(gn, N_NODES - 1) : gn;  // x is unpadded
        float4 m = ((const float4*)g_mean)[(size_t)gn * 16 + c];
        float4 s = ((const float4*)selfF)[(size_t)cn * 16 + c];
        ulonglong2* mp = (ulonglong2*)&sMd[n * SM_STRIDE + 4 * c];
        ulonglong2* sp = (ulonglong2*)&sSd[n * SM_STRIDE + 4 * c];
        ulonglong2 mv, sv;
        mv.x = pk2(m.x, m.x); mv.y = pk2(m.y, m.y);
        mp[0] = mv;
        mv.x = pk2(m.z, m.z); mv.y = pk2(m.w, m.w);
        mp[1] = mv;
        sv.x = pk2(s.x, s.x); sv.y = pk2(s.y, s.y);
        sp[0] = sv;
        sv.x = pk2(s.z, s.z); sv.y = pk2(s.w, s.w);
        sp[1] = sv;
    }
    __syncthreads();

    float4 b4 = *(const float4*)&bias[og * 4];
    ull acc[4][2];
    #pragma unroll
    for (int n = 0; n < 4; ++n) {
        acc[n][0] = pk2(b4.x, b4.y);
        acc[n][1] = pk2(b4.z, b4.w);
    }

    const ull* mrow = &sMd[(ng * 4) * SM_STRIDE];
    const ull* srow = &sSd[(ng * 4) * SM_STRIDE];

    #pragma unroll 4
    for (int k = 0; k < C; k += 2) {
        ulonglong2 wl0 = *(const ulonglong2*)&sWl[k * SW_STRIDE + og * 4];
        ulonglong2 wl1 = *(const ulonglong2*)&sWl[(k + 1) * SW_STRIDE + og * 4];
        ulonglong2 wr0 = *(const ulonglong2*)&sWr[k * SW_STRIDE + og * 4];
        ulonglong2 wr1 = *(const ulonglong2*)&sWr[(k + 1) * SW_STRIDE + og * 4];
        ulonglong2 mv[4], sv[4];
        #pragma unroll
        for (int n = 0; n < 4; ++n) mv[n] = *(const ulonglong2*)&mrow[n * SM_STRIDE + k];
        #pragma unroll
        for (int n = 0; n < 4; ++n) sv[n] = *(const ulonglong2*)&srow[n * SM_STRIDE + k];
        #pragma unroll
        for (int n = 0; n < 4; ++n) {
            acc[n][0] = fma2(mv[n].x, wl0.x, acc[n][0]);
            acc[n][1] = fma2(mv[n].x, wl0.y, acc[n][1]);
            acc[n][0] = fma2(mv[n].y, wl1.x, acc[n][0]);
            acc[n][1] = fma2(mv[n].y, wl1.y, acc[n][1]);
        }
        #pragma unroll
        for (int n = 0; n < 4; ++n) {
            acc[n][0] = fma2(sv[n].x, wr0.x, acc[n][0]);
            acc[n][1] = fma2(sv[n].x, wr0.y, acc[n][1]);
            acc[n][0] = fma2(sv[n].y, wr1.x, acc[n][0]);
            acc[n][1] = fma2(sv[n].y, wr1.y, acc[n][1]);
        }
    }

    if (LAYER == 1) {
        #pragma unroll
        for (int n = 0; n < 4; ++n) {
            float4 r;
            unpk2(acc[n][0], r.x, r.y);
            unpk2(acc[n][1], r.z, r.w);
            r.x = fmaxf(r.x, 0.f); r.y = fmaxf(r.y, 0.f);
            r.z = fmaxf(r.z, 0.f); r.w = fmaxf(r.w, 0.f);
            int gn = base + ng * 4 + n;
            ((float4*)g_h1)[(size_t)gn * 16 + og] = r;   // gn < N_PAD
        }
    } else {
        float4 wo = *(const float4*)&w_out[og * 4];
        float bo = b_out[0];
        #pragma unroll
        for (int n = 0; n < 4; ++n) {
            float r0, r1, r2, r3;
            unpk2(acc[n][0], r0, r1);
            unpk2(acc[n][1], r2, r3);
            r0 = fmaxf(r0, 0.f); r1 = fmaxf(r1, 0.f);
            r2 = fmaxf(r2, 0.f); r3 = fmaxf(r3, 0.f);
            float p = r0 * wo.x + r1 * wo.y + r2 * wo.z + r3 * wo.w;
            // reduce over the 16 og lanes (xor 1,2,4,8 stays in og group)
            p += __shfl_xor_sync(0xffffffffu, p, 1);
            p += __shfl_xor_sync(0xffffffffu, p, 2);
            p += __shfl_xor_sync(0xffffffffu, p, 4);
            p += __shfl_xor_sync(0xffffffffu, p, 8);
            if (og == 0) {
                int gn = base + ng * 4 + n;
                if (gn < N_NODES) {
                    out[gn] = 1.0f / (1.0f + expf(-(p + bo)));
                }
            }
        }
    }
}

// ========================= launch ============================================
extern "C" void kernel_launch(void* const* d_in, const int* in_sizes, int n_in,
                              void* d_out, int out_size) {
    const float* x     = (const float*)d_in[0];
    const int*   ei    = (const int*)  d_in[1];
    const float* w1_l  = (const float*)d_in[2];
    const float* b1    = (const float*)d_in[3];
    const float* w1_r  = (const float*)d_in[4];
    const float* w2_l  = (const float*)d_in[5];
    const float* b2    = (const float*)d_in[6];
    const float* w2_r  = (const float*)d_in[7];
    const float* w_out = (const float*)d_in[8];
    const float* b_out = (const float*)d_in[9];
    float* out = (float*)d_out;

    const int* src = ei;
    const int* dst = ei + N_EDGES;

    cudaFuncSetAttribute(node_kernel<1>, cudaFuncAttributeMaxDynamicSharedMemorySize, SMEM_BYTES);
    cudaFuncSetAttribute(node_kernel<2>, cudaFuncAttributeMaxDynamicSharedMemorySize, SMEM_BYTES);

    const int EB  = (N_EDGES + 255) / 256;            // 3907
    const int EB4 = (N_EDGES / 4 + 255) / 256;        // 977
    const int AB  = (N_PAD * 16) / 256;               // 6252
    const int NB  = N_PAD / 64;                       // 1563

    // ---- CSR build ----
    zero_kernel<<<SCAN_BLOCKS, 1024>>>();
    deg_kernel<<<EB4, 256>>>(dst);
    scan_kernel<<<SCAN_BLOCKS, 1024>>>();
    fill_kernel<<<EB, 256>>>(src, dst);

    // ---- layer 1 ----
    agg_mean_kernel<1><<<AB, 256>>>(x);
    node_kernel<1><<<NB, 256, SMEM_BYTES>>>(x, w1_l, b1, w1_r, w_out, b_out, out);

    // ---- layer 2 (+ fused sigmoid head) ----
    agg_mean_kernel<2><<<AB, 256>>>(x);
    node_kernel<2><<<NB, 256, SMEM_BYTES>>>(x, w2_l, b2, w2_r, w_out, b_out, out);
}

// round 6
// speedup vs baseline: 1.0965x; 1.0965x over previous
#include <cuda_runtime.h>
#include <math.h>

#define N_NODES 100000
#define N_EDGES 1000000
#define C 64
#define N_PAD 100032            // 1563 * 64
#define SCAN_BLOCKS 98          // 98*1024 >= N_NODES
#define FLAGBIT (1 << 30)

typedef unsigned long long ull;

// ---------------- scratch (device globals; no allocation allowed) -----------
__device__ __align__(16) float g_mean[(size_t)N_PAD * C];
__device__ __align__(16) float g_h1  [(size_t)N_PAD * C];
__device__ int g_deg[N_NODES];
__device__ int g_rowptr[N_NODES + 1];
__device__ int g_cursor[N_NODES];
__device__ int g_col[N_EDGES];
__device__ int g_look[SCAN_BLOCKS];     // decoupled-lookback slots (value | FLAGBIT)

// ---------------- f32x2 packed FMA helpers ----------------------------------
__device__ __forceinline__ ull pk2(float lo, float hi) {
    ull r;
    asm("mov.b64 %0, {%1, %2};" : "=l"(r) : "f"(lo), "f"(hi));
    return r;
}
__device__ __forceinline__ ull fma2(ull a, ull b, ull c) {
    ull d;
    asm("fma.rn.f32x2 %0, %1, %2, %3;" : "=l"(d) : "l"(a), "l"(b), "l"(c));
    return d;
}
__device__ __forceinline__ void unpk2(ull v, float& lo, float& hi) {
    asm("mov.b64 {%0, %1}, %2;" : "=f"(lo), "=f"(hi) : "l"(v));
}

// ========================= CSR build =========================================
__global__ void zero_kernel() {
    int i = blockIdx.x * 1024 + threadIdx.x;
    if (i < N_NODES) g_deg[i] = 0;
    if (i < SCAN_BLOCKS) g_look[i] = 0;
}

// 4 edges per thread, vectorized index load; independent RED ops pipeline.
__global__ void deg_kernel(const int* __restrict__ dst) {
    int e4 = blockIdx.x * blockDim.x + threadIdx.x;
    if (e4 * 4 + 3 < N_EDGES) {
        int4 d = ((const int4*)dst)[e4];
        atomicAdd(&g_deg[d.x], 1);
        atomicAdd(&g_deg[d.y], 1);
        atomicAdd(&g_deg[d.z], 1);
        atomicAdd(&g_deg[d.w], 1);
    } else {
        for (int e = e4 * 4; e < N_EDGES; ++e) atomicAdd(&g_deg[dst[e]], 1);
    }
}

// single-pass scan: warp-shuffle block scan + decoupled lookback over block
// aggregates. All 98 blocks fit in one wave (<=148 SMs) -> spin is safe.
__global__ void __launch_bounds__(1024) scan_kernel() {
    __shared__ int swarp[32];
    __shared__ int sprefix;
    int t = threadIdx.x;
    int b = blockIdx.x;
    int i = b * 1024 + t;
    int lane = t & 31;
    int wid = t >> 5;

    int deg = (i < N_NODES) ? g_deg[i] : 0;

    int v = deg;
    #pragma unroll
    for (int off = 1; off < 32; off <<= 1) {
        int u = __shfl_up_sync(0xffffffffu, v, off);
        if (lane >= off) v += u;
    }
    if (lane == 31) swarp[wid] = v;
    __syncthreads();
    if (wid == 0) {
        int w = swarp[lane];
        #pragma unroll
        for (int off = 1; off < 32; off <<= 1) {
            int u = __shfl_up_sync(0xffffffffu, w, off);
            if (lane >= off) w += u;
        }
        swarp[lane] = w;
    }
    __syncthreads();
    int incl = v + (wid > 0 ? swarp[wid - 1] : 0);   // block-local inclusive
    int total = swarp[31];

    if (t == 0) atomicExch(&g_look[b], total | FLAGBIT);
    if (wid == 0) {
        int run = 0;
        for (int base = 0; base < b; base += 32) {
            int idx = base + lane;
            int a = 0;
            if (idx < b) {
                do { a = atomicAdd(&g_look[idx], 0); } while (!(a & FLAGBIT));
                a &= ~FLAGBIT;
            }
            #pragma unroll
            for (int off = 16; off > 0; off >>= 1)
                a += __shfl_xor_sync(0xffffffffu, a, off);
            run += a;
        }
        if (lane == 0) sprefix = run;
    }
    __syncthreads();

    if (i < N_NODES) {
        int gincl = sprefix + incl;
        g_rowptr[i + 1] = gincl;
        g_cursor[i] = gincl - deg;
        if (i == 0) g_rowptr[0] = 0;
    }
}

// 4 edges per thread: independent atomicAdd cursor claims pipeline (MLP=4)
// instead of one 318-cyc L2 round trip per thread.
__global__ void fill_kernel(const int* __restrict__ src, const int* __restrict__ dst) {
    int e4 = blockIdx.x * blockDim.x + threadIdx.x;
    int e = e4 * 4;
    if (e + 3 < N_EDGES) {
        int4 d = ((const int4*)dst)[e4];
        int4 s = ((const int4*)src)[e4];
        int p0 = atomicAdd(&g_cursor[d.x], 1);
        int p1 = atomicAdd(&g_cursor[d.y], 1);
        int p2 = atomicAdd(&g_cursor[d.z], 1);
        int p3 = atomicAdd(&g_cursor[d.w], 1);
        g_col[p0] = s.x;
        g_col[p1] = s.y;
        g_col[p2] = s.z;
        g_col[p3] = s.w;
    } else {
        for (; e < N_EDGES; ++e) {
            int pos = atomicAdd(&g_cursor[dst[e]], 1);
            g_col[pos] = src[e];
        }
    }
}

// ========================= mean aggregation ==================================
// (proven R4 version) 16 threads per node, unroll-2.
template <int LAYER>
__global__ void __launch_bounds__(256) agg_mean_kernel(const float* __restrict__ x_ext) {
    int idx = blockIdx.x * 256 + threadIdx.x;
    int n = idx >> 4;
    int c = idx & 15;
    if (n >= N_NODES) {
        ((float4*)g_mean)[(size_t)n * 16 + c] = make_float4(0.f, 0.f, 0.f, 0.f);
        return;
    }
    const float4* f4 = (LAYER == 1) ? (const float4*)x_ext : (const float4*)g_h1;
    int beg = g_rowptr[n];
    int end = g_rowptr[n + 1];
    float4 acc = make_float4(0.f, 0.f, 0.f, 0.f);
    int j = beg;
    for (; j + 1 < end; j += 2) {
        int s0 = g_col[j];
        int s1 = g_col[j + 1];
        float4 a = f4[(size_t)s0 * 16 + c];
        float4 b = f4[(size_t)s1 * 16 + c];
        acc.x += a.x + b.x; acc.y += a.y + b.y;
        acc.z += a.z + b.z; acc.w += a.w + b.w;
    }
    if (j < end) {
        int s0 = g_col[j];
        float4 a = f4[(size_t)s0 * 16 + c];
        acc.x += a.x; acc.y += a.y; acc.z += a.z; acc.w += a.w;
    }
    float inv = 1.0f / fmaxf((float)(end - beg), 1.0f);
    acc.x *= inv; acc.y *= inv; acc.z *= inv; acc.w *= inv;
    ((float4*)g_mean)[(size_t)n * 16 + c] = acc;
}

// ========================= node GEMM (proven R4 version) =====================
// 128 threads, 64 nodes/block. og = t&15 (outputs 4og..4og+3), ng = t>>4
// (nodes 8ng..8ng+7). Mean/self duplicated as (v,v) u64; weights transposed.
#define SW_STRIDE 68            // floats per weight row
#define SM_STRIDE 65            // u64 per node row
#define SMEM_BYTES (2*64*SW_STRIDE*4 + 2*64*SM_STRIDE*8)   // 101376

template <int LAYER>
__global__ void __launch_bounds__(128) node_kernel(
        const float* __restrict__ x_ext,
        const float* __restrict__ Wl,
        const float* __restrict__ bias,
        const float* __restrict__ Wr,
        const float* __restrict__ w_out,
        const float* __restrict__ b_out,
        float* __restrict__ out) {
    extern __shared__ char smraw[];
    float* sWl = (float*)smraw;                       // [64][SW_STRIDE]
    float* sWr = sWl + 64 * SW_STRIDE;
    ull* sMd = (ull*)(sWr + 64 * SW_STRIDE);          // [64][SM_STRIDE]
    ull* sSd = sMd + 64 * SM_STRIDE;

    const float* selfF = (LAYER == 1) ? x_ext : (const float*)g_h1;

    int t = threadIdx.x;
    int og = t & 15;
    int ng = t >> 4;
    int base = blockIdx.x * 64;

    #pragma unroll
    for (int i = t; i < 64 * 64; i += 128) {
        int o = i >> 6, k = i & 63;
        sWl[k * SW_STRIDE + o] = Wl[i];
        sWr[k * SW_STRIDE + o] = Wr[i];
    }

    #pragma unroll
    for (int it = 0; it < 8; ++it) {
        int item = it * 128 + t;
        int n = item & 63;
        int c = item >> 6;
        int gn = base + n;
        int cn = (LAYER == 1) ? min(gn, N_NODES - 1) : gn;
        float4 m = ((const float4*)g_mean)[(size_t)gn * 16 + c];
        float4 s = ((const float4*)selfF)[(size_t)cn * 16 + c];
        ull* mp = &sMd[n * SM_STRIDE + 4 * c];
        ull* sp = &sSd[n * SM_STRIDE + 4 * c];
        mp[0] = pk2(m.x, m.x); mp[1] = pk2(m.y, m.y);
        mp[2] = pk2(m.z, m.z); mp[3] = pk2(m.w, m.w);
        sp[0] = pk2(s.x, s.x); sp[1] = pk2(s.y, s.y);
        sp[2] = pk2(s.z, s.z); sp[3] = pk2(s.w, s.w);
    }
    __syncthreads();

    float4 b4 = *(const float4*)&bias[og * 4];
    ull acc[8][2];
    #pragma unroll
    for (int n = 0; n < 8; ++n) {
        acc[n][0] = pk2(b4.x, b4.y);
        acc[n][1] = pk2(b4.z, b4.w);
    }

    const ull* mrow = &sMd[(ng * 8) * SM_STRIDE];
    const ull* srow = &sSd[(ng * 8) * SM_STRIDE];

    #pragma unroll 4
    for (int k = 0; k < C; ++k) {
        ulonglong2 wl = *(const ulonglong2*)&sWl[k * SW_STRIDE + og * 4];
        ulonglong2 wr = *(const ulonglong2*)&sWr[k * SW_STRIDE + og * 4];
        ull mv[8], sv[8];
        #pragma unroll
        for (int n = 0; n < 8; ++n) {
            mv[n] = mrow[n * SM_STRIDE + k];
            sv[n] = srow[n * SM_STRIDE + k];
        }
        #pragma unroll
        for (int n = 0; n < 8; ++n) {
            acc[n][0] = fma2(mv[n], wl.x, acc[n][0]);
            acc[n][1] = fma2(mv[n], wl.y, acc[n][1]);
        }
        #pragma unroll
        for (int n = 0; n < 8; ++n) {
            acc[n][0] = fma2(sv[n], wr.x, acc[n][0]);
            acc[n][1] = fma2(sv[n], wr.y, acc[n][1]);
        }
    }

    if (LAYER == 1) {
        #pragma unroll
        for (int n = 0; n < 8; ++n) {
            float4 r;
            unpk2(acc[n][0], r.x, r.y);
            unpk2(acc[n][1], r.z, r.w);
            r.x = fmaxf(r.x, 0.f); r.y = fmaxf(r.y, 0.f);
            r.z = fmaxf(r.z, 0.f); r.w = fmaxf(r.w, 0.f);
            int gn = base + ng * 8 + n;
            ((float4*)g_h1)[(size_t)gn * 16 + og] = r;   // gn < N_PAD
        }
    } else {
        float4 wo = *(const float4*)&w_out[og * 4];
        float bo = b_out[0];
        #pragma unroll
        for (int n = 0; n < 8; ++n) {
            float r0, r1, r2, r3;
            unpk2(acc[n][0], r0, r1);
            unpk2(acc[n][1], r2, r3);
            r0 = fmaxf(r0, 0.f); r1 = fmaxf(r1, 0.f);
            r2 = fmaxf(r2, 0.f); r3 = fmaxf(r3, 0.f);
            float p = r0 * wo.x + r1 * wo.y + r2 * wo.z + r3 * wo.w;
            p += __shfl_xor_sync(0xffffffffu, p, 1);
            p += __shfl_xor_sync(0xffffffffu, p, 2);
            p += __shfl_xor_sync(0xffffffffu, p, 4);
            p += __shfl_xor_sync(0xffffffffu, p, 8);
            if (og == 0) {
                int gn = base + ng * 8 + n;
                if (gn < N_NODES) {
                    out[gn] = 1.0f / (1.0f + expf(-(p + bo)));
                }
            }
        }
    }
}

// ========================= launch ============================================
extern "C" void kernel_launch(void* const* d_in, const int* in_sizes, int n_in,
                              void* d_out, int out_size) {
    const float* x     = (const float*)d_in[0];
    const int*   ei    = (const int*)  d_in[1];
    const float* w1_l  = (const float*)d_in[2];
    const float* b1    = (const float*)d_in[3];
    const float* w1_r  = (const float*)d_in[4];
    const float* w2_l  = (const float*)d_in[5];
    const float* b2    = (const float*)d_in[6];
    const float* w2_r  = (const float*)d_in[7];
    const float* w_out = (const float*)d_in[8];
    const float* b_out = (const float*)d_in[9];
    float* out = (float*)d_out;

    const int* src = ei;
    const int* dst = ei + N_EDGES;

    cudaFuncSetAttribute(node_kernel<1>, cudaFuncAttributeMaxDynamicSharedMemorySize, SMEM_BYTES);
    cudaFuncSetAttribute(node_kernel<2>, cudaFuncAttributeMaxDynamicSharedMemorySize, SMEM_BYTES);

    const int EB4 = (N_EDGES / 4 + 255) / 256;        // 977
    const int AB  = (N_PAD * 16) / 256;               // 6252
    const int NB  = N_PAD / 64;                       // 1563

    // ---- CSR build ----
    zero_kernel<<<SCAN_BLOCKS, 1024>>>();
    deg_kernel<<<EB4, 256>>>(dst);
    scan_kernel<<<SCAN_BLOCKS, 1024>>>();
    fill_kernel<<<EB4, 256>>>(src, dst);

    // ---- layer 1 ----
    agg_mean_kernel<1><<<AB, 256>>>(x);
    node_kernel<1><<<NB, 128, SMEM_BYTES>>>(x, w1_l, b1, w1_r, w_out, b_out, out);

    // ---- layer 2 (+ fused sigmoid head) ----
    agg_mean_kernel<2><<<AB, 256>>>(x);
    node_kernel<2><<<NB, 128, SMEM_BYTES>>>(x, w2_l, b2, w2_r, w_out, b_out, out);
}

// round 8
// speedup vs baseline: 1.1223x; 1.0235x over previous
#include <cuda_runtime.h>
#include <math.h>

#define N_NODES 100000
#define N_EDGES 1000000
#define C 64
#define N_PAD 100032            // 1563 * 64
#define SCAN_BLOCKS 98          // 98*1024 >= N_NODES
#define FLAGBIT (1 << 30)

typedef unsigned long long ull;

// ---------------- scratch (device globals; no allocation allowed) -----------
__device__ __align__(16) float g_mean[(size_t)N_PAD * C];
__device__ __align__(16) float g_h1  [(size_t)N_PAD * C];
__device__ int g_deg[N_NODES];
__device__ int g_rowptr[N_NODES + 1];
__device__ int g_cursor[N_NODES];
__device__ int g_col[N_EDGES];
__device__ int g_look[SCAN_BLOCKS];     // decoupled-lookback slots (value | FLAGBIT)

// ---------------- f32x2 packed FMA helpers ----------------------------------
__device__ __forceinline__ ull pk2(float lo, float hi) {
    ull r;
    asm("mov.b64 %0, {%1, %2};" : "=l"(r) : "f"(lo), "f"(hi));
    return r;
}
__device__ __forceinline__ ull fma2(ull a, ull b, ull c) {
    ull d;
    asm("fma.rn.f32x2 %0, %1, %2, %3;" : "=l"(d) : "l"(a), "l"(b), "l"(c));
    return d;
}
__device__ __forceinline__ void unpk2(ull v, float& lo, float& hi) {
    asm("mov.b64 {%0, %1}, %2;" : "=f"(lo), "=f"(hi) : "l"(v));
}

// ========================= CSR build (unchanged R6) ==========================
__global__ void zero_kernel() {
    int i = blockIdx.x * 1024 + threadIdx.x;
    if (i < N_NODES) g_deg[i] = 0;
    if (i < SCAN_BLOCKS) g_look[i] = 0;
}

__global__ void deg_kernel(const int* __restrict__ dst) {
    int e4 = blockIdx.x * blockDim.x + threadIdx.x;
    if (e4 * 4 + 3 < N_EDGES) {
        int4 d = ((const int4*)dst)[e4];
        atomicAdd(&g_deg[d.x], 1);
        atomicAdd(&g_deg[d.y], 1);
        atomicAdd(&g_deg[d.z], 1);
        atomicAdd(&g_deg[d.w], 1);
    } else {
        for (int e = e4 * 4; e < N_EDGES; ++e) atomicAdd(&g_deg[dst[e]], 1);
    }
}

__global__ void __launch_bounds__(1024) scan_kernel() {
    __shared__ int swarp[32];
    __shared__ int sprefix;
    int t = threadIdx.x;
    int b = blockIdx.x;
    int i = b * 1024 + t;
    int lane = t & 31;
    int wid = t >> 5;

    int deg = (i < N_NODES) ? g_deg[i] : 0;

    int v = deg;
    #pragma unroll
    for (int off = 1; off < 32; off <<= 1) {
        int u = __shfl_up_sync(0xffffffffu, v, off);
        if (lane >= off) v += u;
    }
    if (lane == 31) swarp[wid] = v;
    __syncthreads();
    if (wid == 0) {
        int w = swarp[lane];
        #pragma unroll
        for (int off = 1; off < 32; off <<= 1) {
            int u = __shfl_up_sync(0xffffffffu, w, off);
            if (lane >= off) w += u;
        }
        swarp[lane] = w;
    }
    __syncthreads();
    int incl = v + (wid > 0 ? swarp[wid - 1] : 0);
    int total = swarp[31];

    if (t == 0) atomicExch(&g_look[b], total | FLAGBIT);
    if (wid == 0) {
        int run = 0;
        for (int base = 0; base < b; base += 32) {
            int idx = base + lane;
            int a = 0;
            if (idx < b) {
                do { a = atomicAdd(&g_look[idx], 0); } while (!(a & FLAGBIT));
                a &= ~FLAGBIT;
            }
            #pragma unroll
            for (int off = 16; off > 0; off >>= 1)
                a += __shfl_xor_sync(0xffffffffu, a, off);
            run += a;
        }
        if (lane == 0) sprefix = run;
    }
    __syncthreads();

    if (i < N_NODES) {
        int gincl = sprefix + incl;
        g_rowptr[i + 1] = gincl;
        g_cursor[i] = gincl - deg;
        if (i == 0) g_rowptr[0] = 0;
    }
}

__global__ void fill_kernel(const int* __restrict__ src, const int* __restrict__ dst) {
    int e4 = blockIdx.x * blockDim.x + threadIdx.x;
    int e = e4 * 4;
    if (e + 3 < N_EDGES) {
        int4 d = ((const int4*)dst)[e4];
        int4 s = ((const int4*)src)[e4];
        int p0 = atomicAdd(&g_cursor[d.x], 1);
        int p1 = atomicAdd(&g_cursor[d.y], 1);
        int p2 = atomicAdd(&g_cursor[d.z], 1);
        int p3 = atomicAdd(&g_cursor[d.w], 1);
        g_col[p0] = s.x;
        g_col[p1] = s.y;
        g_col[p2] = s.z;
        g_col[p3] = s.w;
    } else {
        for (; e < N_EDGES; ++e) {
            int pos = atomicAdd(&g_cursor[dst[e]], 1);
            g_col[pos] = src[e];
        }
    }
}

// ========================= mean aggregation (unchanged R6) ===================
template <int LAYER>
__global__ void __launch_bounds__(256) agg_mean_kernel(const float* __restrict__ x_ext) {
    int idx = blockIdx.x * 256 + threadIdx.x;
    int n = idx >> 4;
    int c = idx & 15;
    if (n >= N_NODES) {
        ((float4*)g_mean)[(size_t)n * 16 + c] = make_float4(0.f, 0.f, 0.f, 0.f);
        return;
    }
    const float4* f4 = (LAYER == 1) ? (const float4*)x_ext : (const float4*)g_h1;
    int beg = g_rowptr[n];
    int end = g_rowptr[n + 1];
    float4 acc = make_float4(0.f, 0.f, 0.f, 0.f);
    int j = beg;
    for (; j + 1 < end; j += 2) {
        int s0 = g_col[j];
        int s1 = g_col[j + 1];
        float4 a = f4[(size_t)s0 * 16 + c];
        float4 b = f4[(size_t)s1 * 16 + c];
        acc.x += a.x + b.x; acc.y += a.y + b.y;
        acc.z += a.z + b.z; acc.w += a.w + b.w;
    }
    if (j < end) {
        int s0 = g_col[j];
        float4 a = f4[(size_t)s0 * 16 + c];
        acc.x += a.x; acc.y += a.y; acc.z += a.z; acc.w += a.w;
    }
    float inv = 1.0f / fmaxf((float)(end - beg), 1.0f);
    acc.x *= inv; acc.y *= inv; acc.z *= inv; acc.w *= inv;
    ((float4*)g_mean)[(size_t)n * 16 + c] = acc;
}

// ========================= node GEMM =========================================
// R4-proven geometry: 128 threads, 64 nodes/block, og = t&15 (outputs
// 4og..4og+3), ng = t>>4 (nodes 8ng..8ng+7). ONE change vs R6: k unrolled by 2
// with value loads as ulonglong2 (one LDS.128 covers k,k+1) -> per 2k:
// 20 LDS + 64 fma2 instead of 36 LDS + 64 fma2. SM_STRIDE even for alignment.
#define SW_STRIDE 68            // floats per weight row
#define SM_STRIDE 66            // u64 per node row (even -> 16B-aligned ull2)
#define SMEM_BYTES (2*64*SW_STRIDE*4 + 2*64*SM_STRIDE*8)   // 34816+67584=102400

template <int LAYER>
__global__ void __launch_bounds__(128) node_kernel(
        const float* __restrict__ x_ext,
        const float* __restrict__ Wl,
        const float* __restrict__ bias,
        const float* __restrict__ Wr,
        const float* __restrict__ w_out,
        const float* __restrict__ b_out,
        float* __restrict__ out) {
    extern __shared__ char smraw[];
    float* sWl = (float*)smraw;                       // [64][SW_STRIDE]
    float* sWr = sWl + 64 * SW_STRIDE;
    ull* sMd = (ull*)(sWr + 64 * SW_STRIDE);          // [64][SM_STRIDE]
    ull* sSd = sMd + 64 * SM_STRIDE;

    const float* selfF = (LAYER == 1) ? x_ext : (const float*)g_h1;

    int t = threadIdx.x;
    int og = t & 15;
    int ng = t >> 4;
    int base = blockIdx.x * 64;

    #pragma unroll
    for (int i = t; i < 64 * 64; i += 128) {
        int o = i >> 6, k = i & 63;
        sWl[k * SW_STRIDE + o] = Wl[i];
        sWr[k * SW_STRIDE + o] = Wr[i];
    }

    #pragma unroll
    for (int it = 0; it < 8; ++it) {
        int item = it * 128 + t;
        int n = item & 63;
        int c = item >> 6;
        int gn = base + n;
        int cn = (LAYER == 1) ? min(gn, N_NODES - 1) : gn;
        float4 m = ((const float4*)g_mean)[(size_t)gn * 16 + c];
        float4 s = ((const float4*)selfF)[(size_t)cn * 16 + c];
        ulonglong2* mp = (ulonglong2*)&sMd[n * SM_STRIDE + 4 * c];
        ulonglong2* sp = (ulonglong2*)&sSd[n * SM_STRIDE + 4 * c];
        ulonglong2 v;
        v.x = pk2(m.x, m.x); v.y = pk2(m.y, m.y);
        mp[0] = v;
        v.x = pk2(m.z, m.z); v.y = pk2(m.w, m.w);
        mp[1] = v;
        v.x = pk2(s.x, s.x); v.y = pk2(s.y, s.y);
        sp[0] = v;
        v.x = pk2(s.z, s.z); v.y = pk2(s.w, s.w);
        sp[1] = v;
    }
    __syncthreads();

    float4 b4 = *(const float4*)&bias[og * 4];
    ull acc[8][2];
    #pragma unroll
    for (int n = 0; n < 8; ++n) {
        acc[n][0] = pk2(b4.x, b4.y);
        acc[n][1] = pk2(b4.z, b4.w);
    }

    const ull* mrow = &sMd[(ng * 8) * SM_STRIDE];
    const ull* srow = &sSd[(ng * 8) * SM_STRIDE];

    #pragma unroll 4
    for (int k = 0; k < C; k += 2) {
        ulonglong2 wl0 = *(const ulonglong2*)&sWl[k * SW_STRIDE + og * 4];
        ulonglong2 wl1 = *(const ulonglong2*)&sWl[(k + 1) * SW_STRIDE + og * 4];
        ulonglong2 wr0 = *(const ulonglong2*)&sWr[k * SW_STRIDE + og * 4];
        ulonglong2 wr1 = *(const ulonglong2*)&sWr[(k + 1) * SW_STRIDE + og * 4];
        {
            ulonglong2 mv[8];
            #pragma unroll
            for (int n = 0; n < 8; ++n)
                mv[n] = *(const ulonglong2*)&mrow[n * SM_STRIDE + k];
            #pragma unroll
            for (int n = 0; n < 8; ++n) {
                acc[n][0] = fma2(mv[n].x, wl0.x, acc[n][0]);
                acc[n][1] = fma2(mv[n].x, wl0.y, acc[n][1]);
            }
            #pragma unroll
            for (int n = 0; n < 8; ++n) {
                acc[n][0] = fma2(mv[n].y, wl1.x, acc[n][0]);
                acc[n][1] = fma2(mv[n].y, wl1.y, acc[n][1]);
            }
        }
        {
            ulonglong2 sv[8];
            #pragma unroll
            for (int n = 0; n < 8; ++n)
                sv[n] = *(const ulonglong2*)&srow[n * SM_STRIDE + k];
            #pragma unroll
            for (int n = 0; n < 8; ++n) {
                acc[n][0] = fma2(sv[n].x, wr0.x, acc[n][0]);
                acc[n][1] = fma2(sv[n].x, wr0.y, acc[n][1]);
            }
            #pragma unroll
            for (int n = 0; n < 8; ++n) {
                acc[n][0] = fma2(sv[n].y, wr1.x, acc[n][0]);
                acc[n][1] = fma2(sv[n].y, wr1.y, acc[n][1]);
            }
        }
    }

    if (LAYER == 1) {
        #pragma unroll
        for (int n = 0; n < 8; ++n) {
            float4 r;
            unpk2(acc[n][0], r.x, r.y);
            unpk2(acc[n][1], r.z, r.w);
            r.x = fmaxf(r.x, 0.f); r.y = fmaxf(r.y, 0.f);
            r.z = fmaxf(r.z, 0.f); r.w = fmaxf(r.w, 0.f);
            int gn = base + ng * 8 + n;
            ((float4*)g_h1)[(size_t)gn * 16 + og] = r;   // gn < N_PAD
        }
    } else {
        float4 wo = *(const float4*)&w_out[og * 4];
        float bo = b_out[0];
        #pragma unroll
        for (int n = 0; n < 8; ++n) {
            float r0, r1, r2, r3;
            unpk2(acc[n][0], r0, r1);
            unpk2(acc[n][1], r2, r3);
            r0 = fmaxf(r0, 0.f); r1 = fmaxf(r1, 0.f);
            r2 = fmaxf(r2, 0.f); r3 = fmaxf(r3, 0.f);
            float p = r0 * wo.x + r1 * wo.y + r2 * wo.z + r3 * wo.w;
            p += __shfl_xor_sync(0xffffffffu, p, 1);
            p += __shfl_xor_sync(0xffffffffu, p, 2);
            p += __shfl_xor_sync(0xffffffffu, p, 4);
            p += __shfl_xor_sync(0xffffffffu, p, 8);
            if (og == 0) {
                int gn = base + ng * 8 + n;
                if (gn < N_NODES) {
                    out[gn] = 1.0f / (1.0f + expf(-(p + bo)));
                }
            }
        }
    }
}

// ========================= launch ============================================
extern "C" void kernel_launch(void* const* d_in, const int* in_sizes, int n_in,
                              void* d_out, int out_size) {
    const float* x     = (const float*)d_in[0];
    const int*   ei    = (const int*)  d_in[1];
    const float* w1_l  = (const float*)d_in[2];
    const float* b1    = (const float*)d_in[3];
    const float* w1_r  = (const float*)d_in[4];
    const float* w2_l  = (const float*)d_in[5];
    const float* b2    = (const float*)d_in[6];
    const float* w2_r  = (const float*)d_in[7];
    const float* w_out = (const float*)d_in[8];
    const float* b_out = (const float*)d_in[9];
    float* out = (float*)d_out;

    const int* src = ei;
    const int* dst = ei + N_EDGES;

    cudaFuncSetAttribute(node_kernel<1>, cudaFuncAttributeMaxDynamicSharedMemorySize, SMEM_BYTES);
    cudaFuncSetAttribute(node_kernel<2>, cudaFuncAttributeMaxDynamicSharedMemorySize, SMEM_BYTES);

    const int EB4 = (N_EDGES / 4 + 255) / 256;        // 977
    const int AB  = (N_PAD * 16) / 256;               // 6252
    const int NB  = N_PAD / 64;                       // 1563

    // ---- CSR build ----
    zero_kernel<<<SCAN_BLOCKS, 1024>>>();
    deg_kernel<<<EB4, 256>>>(dst);
    scan_kernel<<<SCAN_BLOCKS, 1024>>>();
    fill_kernel<<<EB4, 256>>>(src, dst);

    // ---- layer 1 ----
    agg_mean_kernel<1><<<AB, 256>>>(x);
    node_kernel<1><<<NB, 128, SMEM_BYTES>>>(x, w1_l, b1, w1_r, w_out, b_out, out);

    // ---- layer 2 (+ fused sigmoid head) ----
    agg_mean_kernel<2><<<AB, 256>>>(x);
    node_kernel<2><<<NB, 128, SMEM_BYTES>>>(x, w2_l, b2, w2_r, w_out, b_out, out);
}